// round 2
// baseline (speedup 1.0000x reference)
#include <cuda_runtime.h>
#include <cstdint>

// Shapes fixed by the reference:
//   x: [N, 128] f32, adj_row/adj_col: [E] int (32 or 64!), adj_val: [E] f32,
//   W: [128, 64] f32, b: [64] f32  ->  out: [N, 64] f32
#define MAX_NODES 100000
#define F_IN  128
#define F_OUT 64

// Scratch for xw = x @ W (25.6 MB). 16B-aligned for float4 access.
__device__ __align__(16) float g_xw[(size_t)MAX_NODES * F_OUT];
// 1 if adj indices are int64, 0 if int32 (set by detect_kernel each launch).
__device__ int g_idx64;

// ---------------------------------------------------------------------------
// Kernel 0: detect index dtype. For int64 indices (< 2^31) every odd 32-bit
// word is zero; for int32 data the odd words are random node ids (~never all 0).
// ---------------------------------------------------------------------------
__global__ void detect_kernel(const int* __restrict__ row_raw, int n_edges)
{
    int all_zero = 1;
    int limit = n_edges < 64 ? n_edges : 64;
    for (int i = 0; i < limit; i++)
        if (row_raw[2 * i + 1] != 0) { all_zero = 0; break; }
    g_idx64 = all_zero;
}

// ---------------------------------------------------------------------------
// Kernel 1: dense projection xw = x @ W.
// Block = 256 threads, tile = 16 rows x 64 cols. Per k-step per thread:
// 1 broadcast LDS (x) + 1 LDS.128 (W) + 4 FFMA.
// ---------------------------------------------------------------------------
__global__ __launch_bounds__(256) void gemm_kernel(
    const float* __restrict__ x, const float* __restrict__ W,
    float* __restrict__ xw, int n_nodes)
{
    __shared__ float Ws[F_IN][F_OUT];   // 32 KB
    __shared__ float xs[16][F_IN];      //  8 KB

    const int tid = threadIdx.x;
    const int row0 = blockIdx.x * 16;

    const float4* W4 = (const float4*)W;
    float4* Ws4 = (float4*)&Ws[0][0];
    for (int i = tid; i < F_IN * F_OUT / 4; i += 256)
        Ws4[i] = W4[i];

    for (int i = tid; i < 16 * F_IN / 4; i += 256) {
        int r = i / (F_IN / 4);
        int c = i % (F_IN / 4);
        int grow = row0 + r;
        float4 v = make_float4(0.f, 0.f, 0.f, 0.f);
        if (grow < n_nodes)
            v = ((const float4*)(x + (size_t)grow * F_IN))[c];
        ((float4*)&xs[r][0])[c] = v;
    }
    __syncthreads();

    const int r  = tid >> 4;   // 0..15
    const int c4 = tid & 15;   // float4 col 0..15

    float4 acc = make_float4(0.f, 0.f, 0.f, 0.f);
    #pragma unroll
    for (int k = 0; k < F_IN; k++) {
        float a = xs[r][k];
        float4 w = ((const float4*)&Ws[k][0])[c4];
        acc.x += a * w.x;
        acc.y += a * w.y;
        acc.z += a * w.z;
        acc.w += a * w.w;
    }

    int grow = row0 + r;
    if (grow < n_nodes)
        ((float4*)(xw + (size_t)grow * F_OUT))[c4] = acc;
}

// ---------------------------------------------------------------------------
// Kernel 2: out[r][:] = b (out is poisoned by the harness; init needed).
// ---------------------------------------------------------------------------
__global__ __launch_bounds__(256) void bias_init_kernel(
    float* __restrict__ out, const float* __restrict__ b, int n_total4)
{
    int i = blockIdx.x * blockDim.x + threadIdx.x;
    if (i < n_total4)
        ((float4*)out)[i] = ((const float4*)b)[i & (F_OUT / 4 - 1)];
}

// ---------------------------------------------------------------------------
// Kernel 3: edge-parallel scatter: out[row[e]] += val[e] * xw[col[e]].
// 16 threads/edge, one float4 each, red.global.add.v4.f32 (no return trip).
// xw (25.6 MB) and out (25.6 MB) are both L2-resident.
// ---------------------------------------------------------------------------
__global__ __launch_bounds__(256) void spmm_scatter_kernel(
    const void* __restrict__ adj_row,
    const void* __restrict__ adj_col,
    const float* __restrict__ adj_val,
    const float* __restrict__ xw,
    float* __restrict__ out,
    int n_edges, int n_nodes)
{
    long long g = (long long)blockIdx.x * blockDim.x + threadIdx.x;
    int e  = (int)(g >> 4);
    int c4 = (int)(g & 15);
    if (e >= n_edges) return;

    int r, c;
    if (g_idx64) {
        r = (int)((const long long*)adj_row)[e];
        c = (int)((const long long*)adj_col)[e];
    } else {
        r = ((const int*)adj_row)[e];
        c = ((const int*)adj_col)[e];
    }
    // Defensive: wrong-dtype theory shows up as rel_err, not a crash.
    if ((unsigned)r >= (unsigned)n_nodes || (unsigned)c >= (unsigned)n_nodes)
        return;

    float v = adj_val[e];
    float4 m = ((const float4*)(xw + (size_t)c * F_OUT))[c4];
    float* dst = out + (size_t)r * F_OUT + c4 * 4;

    asm volatile(
        "red.global.add.v4.f32 [%0], {%1, %2, %3, %4};"
        :: "l"(dst), "f"(m.x * v), "f"(m.y * v), "f"(m.z * v), "f"(m.w * v)
        : "memory");
}

// ---------------------------------------------------------------------------
// Launch. Inputs (metadata order): x, adj_row, adj_col, adj_val, W, b
// ---------------------------------------------------------------------------
extern "C" void kernel_launch(void* const* d_in, const int* in_sizes, int n_in,
                              void* d_out, int out_size)
{
    const float* x       = (const float*)d_in[0];
    const void*  adj_row = d_in[1];
    const void*  adj_col = d_in[2];
    const float* adj_val = (const float*)d_in[3];
    const float* W       = (const float*)d_in[4];
    const float* b       = (const float*)d_in[5];
    float*       out     = (float*)d_out;

    const int n_nodes = in_sizes[0] / F_IN;
    const int n_edges = in_sizes[3];

    float* xw;
    cudaGetSymbolAddress((void**)&xw, g_xw);

    // 0) index dtype detect
    detect_kernel<<<1, 1>>>((const int*)adj_row, n_edges);

    // 1) xw = x @ W
    gemm_kernel<<<(n_nodes + 15) / 16, 256>>>(x, W, xw, n_nodes);

    // 2) out = broadcast(b)
    int n_total4 = n_nodes * (F_OUT / 4);
    bias_init_kernel<<<(n_total4 + 255) / 256, 256>>>(out, b, n_total4);

    // 3) out += scatter(adj_val * xw[adj_col]) by adj_row
    long long total_threads = (long long)n_edges * 16;
    int scatter_blocks = (int)((total_threads + 255) / 256);
    spmm_scatter_kernel<<<scatter_blocks, 256>>>(adj_row, adj_col, adj_val,
                                                 xw, out, n_edges, n_nodes);
}

// round 5
// speedup vs baseline: 1.4847x; 1.4847x over previous
#include <cuda_runtime.h>
#include <cstdint>

// Shapes fixed by the reference:
//   x: [N, 128] f32, adj_row/adj_col: [E] int32 (declared int64, actually 32 —
//   detected at runtime), adj_val: [E] f32, W: [128, 64] f32, b: [64] f32
//   -> out: [N, 64] f32
#define MAX_NODES 100000
#define F_IN  128
#define F_OUT 64

// Scratch for xw = x @ W (25.6 MB). 16B-aligned for float4 access.
__device__ __align__(16) float g_xw[(size_t)MAX_NODES * F_OUT];
// 1 if adj indices are int64, 0 if int32.
__device__ int g_idx64;

// ---------------------------------------------------------------------------
// Kernel 0: detect index dtype (parallel). For genuine int64 indices (<2^31)
// every odd 32-bit word is zero; int32 data has random ids there.
// ---------------------------------------------------------------------------
__global__ void detect_kernel(const int* __restrict__ row_raw, int n_edges)
{
    __shared__ int any_nonzero;
    int t = threadIdx.x;
    if (t == 0) any_nonzero = 0;
    __syncthreads();
    int limit = n_edges < 64 ? n_edges : 64;
    if (t < limit && row_raw[2 * t + 1] != 0)
        atomicOr(&any_nonzero, 1);
    __syncthreads();
    if (t == 0) g_idx64 = (any_nonzero == 0);
}

// ---------------------------------------------------------------------------
// Kernel 1: xw = x @ W. Block 256, tile 64 rows x 64 cols, register-blocked:
// each thread computes 4 rows x 4 cols (one float4 per row).
// Per k-step: 1 LDS.128 (W) + 4 broadcast LDS (x) feed 16 FFMA.
// Tiles live in 64 KB DYNAMIC smem (static limit is 48 KB).
//   layout: [0, 32KB)  Ws4 (float4[2048], [k][c4])
//           [32KB,64KB) xs  (float[64][128])
// ---------------------------------------------------------------------------
__global__ __launch_bounds__(256) void gemm_kernel(
    const float* __restrict__ x, const float* __restrict__ W,
    float* __restrict__ xw, int n_nodes)
{
    extern __shared__ __align__(16) unsigned char smem_raw[];
    float4* Ws4 = (float4*)smem_raw;                         // 32 KB
    float (*xs)[F_IN] = (float (*)[F_IN])(smem_raw + 32768); // 32 KB

    const int tid = threadIdx.x;
    const int row0 = blockIdx.x * 64;

    // Load W (8192 floats) as float4, layout [k][c4]
    const float4* W4 = (const float4*)W;
    for (int i = tid; i < F_IN * F_OUT / 4; i += 256)
        Ws4[i] = W4[i];

    // Load 64-row x tile
    for (int i = tid; i < 64 * F_IN / 4; i += 256) {
        int r = i / (F_IN / 4);
        int c = i % (F_IN / 4);
        int gr = row0 + r;
        float4 v = make_float4(0.f, 0.f, 0.f, 0.f);
        if (gr < n_nodes)
            v = ((const float4*)(x + (size_t)gr * F_IN))[c];
        ((float4*)&xs[r][0])[c] = v;
    }
    __syncthreads();

    const int c4 = tid & 15;          // float4 column 0..15
    const int r0 = (tid >> 4) * 4;    // first of 4 rows

    float4 acc0 = make_float4(0.f, 0.f, 0.f, 0.f);
    float4 acc1 = acc0, acc2 = acc0, acc3 = acc0;

    #pragma unroll 4
    for (int k = 0; k < F_IN; k++) {
        float4 w = Ws4[k * 16 + c4];
        float a0 = xs[r0 + 0][k];
        float a1 = xs[r0 + 1][k];
        float a2 = xs[r0 + 2][k];
        float a3 = xs[r0 + 3][k];
        acc0.x += a0 * w.x; acc0.y += a0 * w.y; acc0.z += a0 * w.z; acc0.w += a0 * w.w;
        acc1.x += a1 * w.x; acc1.y += a1 * w.y; acc1.z += a1 * w.z; acc1.w += a1 * w.w;
        acc2.x += a2 * w.x; acc2.y += a2 * w.y; acc2.z += a2 * w.z; acc2.w += a2 * w.w;
        acc3.x += a3 * w.x; acc3.y += a3 * w.y; acc3.z += a3 * w.z; acc3.w += a3 * w.w;
    }

    int gr = row0 + r0;
    if (gr + 0 < n_nodes) ((float4*)(xw + (size_t)(gr + 0) * F_OUT))[c4] = acc0;
    if (gr + 1 < n_nodes) ((float4*)(xw + (size_t)(gr + 1) * F_OUT))[c4] = acc1;
    if (gr + 2 < n_nodes) ((float4*)(xw + (size_t)(gr + 2) * F_OUT))[c4] = acc2;
    if (gr + 3 < n_nodes) ((float4*)(xw + (size_t)(gr + 3) * F_OUT))[c4] = acc3;
}

// ---------------------------------------------------------------------------
// Kernel 2: out[r][:] = b (out is poisoned by the harness).
// ---------------------------------------------------------------------------
__global__ __launch_bounds__(256) void bias_init_kernel(
    float* __restrict__ out, const float* __restrict__ b, int n_total4)
{
    int i = blockIdx.x * blockDim.x + threadIdx.x;
    if (i < n_total4)
        ((float4*)out)[i] = ((const float4*)b)[i & (F_OUT / 4 - 1)];
}

// ---------------------------------------------------------------------------
// Kernel 3: edge scatter: out[row[e]] += val[e] * xw[col[e]].
// 4 threads/edge, each thread: 4 independent gather LDG.128 (MLP=4) then
// 4 red.global.add.v4.f32 (no return trip).
// ---------------------------------------------------------------------------
__global__ __launch_bounds__(256) void spmm_scatter_kernel(
    const void* __restrict__ adj_row,
    const void* __restrict__ adj_col,
    const float* __restrict__ adj_val,
    const float* __restrict__ xw,
    float* __restrict__ out,
    int n_edges, int n_nodes)
{
    long long g = (long long)blockIdx.x * blockDim.x + threadIdx.x;
    int e = (int)(g >> 2);
    int q = (int)(g & 3);
    if (e >= n_edges) return;

    int r, c;
    if (g_idx64) {
        r = (int)((const long long*)adj_row)[e];
        c = (int)((const long long*)adj_col)[e];
    } else {
        r = ((const int*)adj_row)[e];
        c = ((const int*)adj_col)[e];
    }
    if ((unsigned)r >= (unsigned)n_nodes || (unsigned)c >= (unsigned)n_nodes)
        return;

    float v = adj_val[e];
    const float4* src = (const float4*)(xw + (size_t)c * F_OUT);
    float*        dst = out + (size_t)r * F_OUT;

    // 4 independent gathers first (MLP=4), then the reductions.
    float4 m0 = src[q + 0];
    float4 m1 = src[q + 4];
    float4 m2 = src[q + 8];
    float4 m3 = src[q + 12];

    asm volatile("red.global.add.v4.f32 [%0], {%1, %2, %3, %4};"
        :: "l"(dst + (q + 0) * 4),
           "f"(m0.x * v), "f"(m0.y * v), "f"(m0.z * v), "f"(m0.w * v) : "memory");
    asm volatile("red.global.add.v4.f32 [%0], {%1, %2, %3, %4};"
        :: "l"(dst + (q + 4) * 4),
           "f"(m1.x * v), "f"(m1.y * v), "f"(m1.z * v), "f"(m1.w * v) : "memory");
    asm volatile("red.global.add.v4.f32 [%0], {%1, %2, %3, %4};"
        :: "l"(dst + (q + 8) * 4),
           "f"(m2.x * v), "f"(m2.y * v), "f"(m2.z * v), "f"(m2.w * v) : "memory");
    asm volatile("red.global.add.v4.f32 [%0], {%1, %2, %3, %4};"
        :: "l"(dst + (q + 12) * 4),
           "f"(m3.x * v), "f"(m3.y * v), "f"(m3.z * v), "f"(m3.w * v) : "memory");
}

// ---------------------------------------------------------------------------
// Launch. Inputs (metadata order): x, adj_row, adj_col, adj_val, W, b
// ---------------------------------------------------------------------------
extern "C" void kernel_launch(void* const* d_in, const int* in_sizes, int n_in,
                              void* d_out, int out_size)
{
    const float* x       = (const float*)d_in[0];
    const void*  adj_row = d_in[1];
    const void*  adj_col = d_in[2];
    const float* adj_val = (const float*)d_in[3];
    const float* W       = (const float*)d_in[4];
    const float* b       = (const float*)d_in[5];
    float*       out     = (float*)d_out;

    const int n_nodes = in_sizes[0] / F_IN;
    const int n_edges = in_sizes[3];

    float* xw;
    cudaGetSymbolAddress((void**)&xw, g_xw);

    // Opt in to 64 KB dynamic smem for the GEMM (not a stream op; capture-safe).
    const int GEMM_SMEM = 65536;
    cudaFuncSetAttribute(gemm_kernel,
                         cudaFuncAttributeMaxDynamicSharedMemorySize, GEMM_SMEM);

    // 0) index dtype detect (parallel)
    detect_kernel<<<1, 64>>>((const int*)adj_row, n_edges);

    // 1) xw = x @ W
    gemm_kernel<<<(n_nodes + 63) / 64, 256, GEMM_SMEM>>>(x, W, xw, n_nodes);

    // 2) out = broadcast(b)
    int n_total4 = n_nodes * (F_OUT / 4);
    bias_init_kernel<<<(n_total4 + 255) / 256, 256>>>(out, b, n_total4);

    // 3) out += scatter(adj_val * xw[adj_col]) by adj_row
    long long total_threads = (long long)n_edges * 4;
    int scatter_blocks = (int)((total_threads + 255) / 256);
    spmm_scatter_kernel<<<scatter_blocks, 256>>>(adj_row, adj_col, adj_val,
                                                 xw, out, n_edges, n_nodes);
}

// round 6
// speedup vs baseline: 1.6941x; 1.1410x over previous
#include <cuda_runtime.h>
#include <cstdint>

// Shapes fixed by the reference:
//   x: [N, 128] f32, adj_row/adj_col: [E] int32 (declared int64, actually 32 —
//   detected at runtime), adj_val: [E] f32, W: [128, 64] f32, b: [64] f32
//   -> out: [N, 64] f32
#define MAX_NODES 131072        // capacity (actual N = 100000)
#define E_CAP     1700000       // capacity (actual E = 1600000)
#define F_IN  128
#define F_OUT 64
#define SCAN_CHUNK 1024
#define SCAN_MAXBLK 128         // ceil(131072/1024)

// ---- static device scratch (no cudaMalloc allowed) ----
__device__ __align__(16) float g_xw[(size_t)MAX_NODES * F_OUT];   // x @ W
__device__ long long g_packed[E_CAP];       // per-edge record: lo32=col, hi32=val bits
__device__ int g_cnt[MAX_NODES];            // per-row edge count
__device__ int g_incl[MAX_NODES];           // per-chunk inclusive scan
__device__ int g_blocktot[SCAN_MAXBLK];     // chunk totals -> chunk offsets
__device__ int g_row_ptr[MAX_NODES + 1];    // CSR row pointers
__device__ int g_cursor[MAX_NODES];         // pack write cursors
__device__ int g_idx64;                     // 1 if adj indices are int64

// ---------------------------------------------------------------------------
// Kernel 0: detect index dtype. int64 indices (<2^31) have all odd words zero.
// ---------------------------------------------------------------------------
__global__ void detect_kernel(const int* __restrict__ row_raw, int n_edges)
{
    __shared__ int any_nonzero;
    int t = threadIdx.x;
    if (t == 0) any_nonzero = 0;
    __syncthreads();
    int limit = n_edges < 64 ? n_edges : 64;
    if (t < limit && row_raw[2 * t + 1] != 0)
        atomicOr(&any_nonzero, 1);
    __syncthreads();
    if (t == 0) g_idx64 = (any_nonzero == 0);
}

__device__ __forceinline__ int load_idx(const void* p, int e)
{
    return g_idx64 ? (int)((const long long*)p)[e] : ((const int*)p)[e];
}

// ---------------------------------------------------------------------------
// Kernel 1: xw = x @ W. 64x64 tile, 4x4 register blocking, 64 KB dynamic smem.
// ---------------------------------------------------------------------------
__global__ __launch_bounds__(256) void gemm_kernel(
    const float* __restrict__ x, const float* __restrict__ W,
    float* __restrict__ xw, int n_nodes)
{
    extern __shared__ __align__(16) unsigned char smem_raw[];
    float4* Ws4 = (float4*)smem_raw;                         // 32 KB, [k][c4]
    float (*xs)[F_IN] = (float (*)[F_IN])(smem_raw + 32768); // 32 KB

    const int tid = threadIdx.x;
    const int row0 = blockIdx.x * 64;

    const float4* W4 = (const float4*)W;
    for (int i = tid; i < F_IN * F_OUT / 4; i += 256)
        Ws4[i] = W4[i];

    for (int i = tid; i < 64 * F_IN / 4; i += 256) {
        int r = i / (F_IN / 4);
        int c = i % (F_IN / 4);
        int gr = row0 + r;
        float4 v = make_float4(0.f, 0.f, 0.f, 0.f);
        if (gr < n_nodes)
            v = ((const float4*)(x + (size_t)gr * F_IN))[c];
        ((float4*)&xs[r][0])[c] = v;
    }
    __syncthreads();

    const int c4 = tid & 15;
    const int r0 = (tid >> 4) * 4;

    float4 acc0 = make_float4(0.f, 0.f, 0.f, 0.f);
    float4 acc1 = acc0, acc2 = acc0, acc3 = acc0;

    #pragma unroll 4
    for (int k = 0; k < F_IN; k++) {
        float4 w = Ws4[k * 16 + c4];
        float a0 = xs[r0 + 0][k];
        float a1 = xs[r0 + 1][k];
        float a2 = xs[r0 + 2][k];
        float a3 = xs[r0 + 3][k];
        acc0.x += a0 * w.x; acc0.y += a0 * w.y; acc0.z += a0 * w.z; acc0.w += a0 * w.w;
        acc1.x += a1 * w.x; acc1.y += a1 * w.y; acc1.z += a1 * w.z; acc1.w += a1 * w.w;
        acc2.x += a2 * w.x; acc2.y += a2 * w.y; acc2.z += a2 * w.z; acc2.w += a2 * w.w;
        acc3.x += a3 * w.x; acc3.y += a3 * w.y; acc3.z += a3 * w.z; acc3.w += a3 * w.w;
    }

    int gr = row0 + r0;
    if (gr + 0 < n_nodes) ((float4*)(xw + (size_t)(gr + 0) * F_OUT))[c4] = acc0;
    if (gr + 1 < n_nodes) ((float4*)(xw + (size_t)(gr + 1) * F_OUT))[c4] = acc1;
    if (gr + 2 < n_nodes) ((float4*)(xw + (size_t)(gr + 2) * F_OUT))[c4] = acc2;
    if (gr + 3 < n_nodes) ((float4*)(xw + (size_t)(gr + 3) * F_OUT))[c4] = acc3;
}

// ---------------------------------------------------------------------------
// CSR build: zero counters -> histogram -> 2-level exclusive scan -> pack.
// ---------------------------------------------------------------------------
__global__ void zero_kernel(int n)
{
    int i = blockIdx.x * blockDim.x + threadIdx.x;
    if (i < n) g_cnt[i] = 0;
}

__global__ void hist_kernel(const void* __restrict__ adj_row,
                            int n_edges, int n_nodes)
{
    int e = blockIdx.x * blockDim.x + threadIdx.x;
    if (e >= n_edges) return;
    int r = load_idx(adj_row, e);
    if ((unsigned)r < (unsigned)n_nodes)
        atomicAdd(&g_cnt[r], 1);   // no return use -> RED
}

// Per-chunk (1024) inclusive scan; writes chunk totals.
__global__ __launch_bounds__(SCAN_CHUNK) void scan_part_kernel(int n)
{
    __shared__ int s[SCAN_CHUNK];
    int t = threadIdx.x;
    int i = blockIdx.x * SCAN_CHUNK + t;
    int v = (i < n) ? g_cnt[i] : 0;
    s[t] = v;
    __syncthreads();
    #pragma unroll
    for (int off = 1; off < SCAN_CHUNK; off <<= 1) {
        int add = (t >= off) ? s[t - off] : 0;
        __syncthreads();
        s[t] += add;
        __syncthreads();
    }
    if (i < n) g_incl[i] = s[t];
    if (t == SCAN_CHUNK - 1) g_blocktot[blockIdx.x] = s[t];
}

// Single block: exclusive-scan the chunk totals in place (nblocks <= 128).
__global__ __launch_bounds__(SCAN_MAXBLK) void scan_top_kernel(int nblocks)
{
    __shared__ int s[SCAN_MAXBLK];
    int t = threadIdx.x;
    int v = (t < nblocks) ? g_blocktot[t] : 0;
    s[t] = v;
    __syncthreads();
    #pragma unroll
    for (int off = 1; off < SCAN_MAXBLK; off <<= 1) {
        int add = (t >= off) ? s[t - off] : 0;
        __syncthreads();
        s[t] += add;
        __syncthreads();
    }
    if (t < nblocks) g_blocktot[t] = s[t] - v;   // exclusive
}

// row_ptr[i+1] = inclusive_scan(cnt)[i]; cursor[i] = row_ptr[i].
__global__ void finalize_kernel(int n)
{
    int i = blockIdx.x * blockDim.x + threadIdx.x;
    if (i >= n) return;
    int inc = g_incl[i] + g_blocktot[i / SCAN_CHUNK];
    g_row_ptr[i + 1] = inc;
    g_cursor[i] = inc - g_cnt[i];
    if (i == 0) g_row_ptr[0] = 0;
}

__global__ void pack_kernel(const void* __restrict__ adj_row,
                            const void* __restrict__ adj_col,
                            const float* __restrict__ adj_val,
                            int n_edges, int n_nodes)
{
    int e = blockIdx.x * blockDim.x + threadIdx.x;
    if (e >= n_edges) return;
    int r = load_idx(adj_row, e);
    int c = load_idx(adj_col, e);
    if ((unsigned)r >= (unsigned)n_nodes || (unsigned)c >= (unsigned)n_nodes)
        return;
    float v = adj_val[e];
    int pos = atomicAdd(&g_cursor[r], 1);
    if (pos < E_CAP)
        g_packed[pos] = ((long long)__float_as_int(v) << 32) | (unsigned)c;
}

// ---------------------------------------------------------------------------
// Aggregate (pull): one 16-lane half-warp per row; float4 accumulator/lane;
// bias fused; coalesced 256B gathers; single coalesced store; no atomics.
// ---------------------------------------------------------------------------
__global__ __launch_bounds__(256) void aggregate_kernel(
    const float* __restrict__ xw, const float* __restrict__ b,
    float* __restrict__ out, int n_nodes)
{
    int g  = blockIdx.x * blockDim.x + threadIdx.x;
    int r  = g >> 4;          // row = half-warp id
    int c4 = g & 15;          // float4 column
    if (r >= n_nodes) return;

    int i   = g_row_ptr[r];
    int end = g_row_ptr[r + 1];

    float4 acc = ((const float4*)b)[c4];
    const float4* xw4 = (const float4*)xw;

    // 4-edge chunks: 4 independent gathers in flight (MLP=4).
    for (; i + 4 <= end; i += 4) {
        long long p0 = g_packed[i + 0];
        long long p1 = g_packed[i + 1];
        long long p2 = g_packed[i + 2];
        long long p3 = g_packed[i + 3];
        int   c0 = (int)p0;  float v0 = __int_as_float((int)(p0 >> 32));
        int   c1 = (int)p1;  float v1 = __int_as_float((int)(p1 >> 32));
        int   c2 = (int)p2;  float v2 = __int_as_float((int)(p2 >> 32));
        int   c3 = (int)p3;  float v3 = __int_as_float((int)(p3 >> 32));
        float4 m0 = xw4[(size_t)c0 * 16 + c4];
        float4 m1 = xw4[(size_t)c1 * 16 + c4];
        float4 m2 = xw4[(size_t)c2 * 16 + c4];
        float4 m3 = xw4[(size_t)c3 * 16 + c4];
        acc.x += v0 * m0.x + v1 * m1.x + v2 * m2.x + v3 * m3.x;
        acc.y += v0 * m0.y + v1 * m1.y + v2 * m2.y + v3 * m3.y;
        acc.z += v0 * m0.z + v1 * m1.z + v2 * m2.z + v3 * m3.z;
        acc.w += v0 * m0.w + v1 * m1.w + v2 * m2.w + v3 * m3.w;
    }
    for (; i < end; i++) {
        long long p = g_packed[i];
        int   c = (int)p;
        float v = __int_as_float((int)(p >> 32));
        float4 m = xw4[(size_t)c * 16 + c4];
        acc.x += v * m.x;  acc.y += v * m.y;
        acc.z += v * m.z;  acc.w += v * m.w;
    }

    ((float4*)out)[(size_t)r * 16 + c4] = acc;
}

// ---------------------------------------------------------------------------
// Launch. Inputs (metadata order): x, adj_row, adj_col, adj_val, W, b
// ---------------------------------------------------------------------------
extern "C" void kernel_launch(void* const* d_in, const int* in_sizes, int n_in,
                              void* d_out, int out_size)
{
    const float* x       = (const float*)d_in[0];
    const void*  adj_row = d_in[1];
    const void*  adj_col = d_in[2];
    const float* adj_val = (const float*)d_in[3];
    const float* W       = (const float*)d_in[4];
    const float* b       = (const float*)d_in[5];
    float*       out     = (float*)d_out;

    const int n_nodes = in_sizes[0] / F_IN;
    const int n_edges = in_sizes[3];

    float* xw;
    cudaGetSymbolAddress((void**)&xw, g_xw);

    const int GEMM_SMEM = 65536;
    cudaFuncSetAttribute(gemm_kernel,
                         cudaFuncAttributeMaxDynamicSharedMemorySize, GEMM_SMEM);

    const int EB = (n_edges + 255) / 256;            // edge-parallel blocks
    const int NB = (n_nodes + 255) / 256;            // node-parallel blocks
    const int SCANB = (n_nodes + SCAN_CHUNK - 1) / SCAN_CHUNK;

    // 0) index dtype detect
    detect_kernel<<<1, 64>>>((const int*)adj_row, n_edges);

    // 1) xw = x @ W
    gemm_kernel<<<(n_nodes + 63) / 64, 256, GEMM_SMEM>>>(x, W, xw, n_nodes);

    // 2) CSR build
    zero_kernel<<<NB, 256>>>(n_nodes);
    hist_kernel<<<EB, 256>>>(adj_row, n_edges, n_nodes);
    scan_part_kernel<<<SCANB, SCAN_CHUNK>>>(n_nodes);
    scan_top_kernel<<<1, SCAN_MAXBLK>>>(SCANB);
    finalize_kernel<<<NB, 256>>>(n_nodes);
    pack_kernel<<<EB, 256>>>(adj_row, adj_col, adj_val, n_edges, n_nodes);

    // 3) pull-based aggregate (bias fused)
    int agg_blocks = (n_nodes * 16 + 255) / 256;
    aggregate_kernel<<<agg_blocks, 256>>>(xw, b, out, n_nodes);
}